// round 9
// baseline (speedup 1.0000x reference)
#include <cuda_runtime.h>

#define TT   2048
#define HB   128
#define NL   3
#define GCTA 32
#define NJ   4
#define NR   16

// Layer 0: K = 8(pad) + 128 = 136 ; layers 1,2: K = 256
#define WOFF0 0
#define WOFF1 (GCTA*NR*136)
#define WOFF2 (WOFF1 + GCTA*NR*256)
#define WTOT  (WOFF2 + GCTA*NR*256)

// h history, PAIR-PACKED: element (l, slot, j, b) at
//   ((l*(TT+1)+slot)*64 + (j>>1))*256 + b*2 + (j&1)
// so {h[j][b], h[j+1][b]} (j even) is one aligned 8-byte word.
__device__ __align__(16) float g_H[(size_t)NL * (TT + 1) * HB * HB];
// x transposed, pair-packed: (t, i, b) at (t*4 + (i>>1))*256 + b*2 + (i&1), i pad 6->8
__device__ __align__(16) float g_xT[TT * 8 * HB];
__device__ float g_Wp[WTOT];
__device__ float g_bias[NL * GCTA * NR];
__device__ int   g_flags[NL * TT];

typedef unsigned long long ull;

__device__ __forceinline__ void upk2(ull v, float& lo, float& hi) {
    asm("mov.b64 {%0,%1},%2;" : "=f"(lo), "=f"(hi) : "l"(v));
}
__device__ __forceinline__ ull ffma2(ull a, ull b, ull c) {
    ull d; asm("fma.rn.f32x2 %0,%1,%2,%3;" : "=l"(d) : "l"(a), "l"(b), "l"(c));
    return d;
}
__device__ __forceinline__ ull ldcg64(const float* p) {
    ull v; asm volatile("ld.global.cg.b64 %0,[%1];" : "=l"(v) : "l"(p));
    return v;
}
__device__ __forceinline__ int ldacq(const int* p) {
    int v; asm volatile("ld.acquire.gpu.global.b32 %0,[%1];" : "=r"(v) : "l"(p) : "memory");
    return v;
}
__device__ __forceinline__ void red_release(int* p) {
    asm volatile("red.release.gpu.global.add.s32 [%0],1;" :: "l"(p) : "memory");
}
__device__ __forceinline__ float sigf(float x) {
    return __fdividef(1.0f, 1.0f + __expf(-x));
}
__device__ __forceinline__ float tanhf_fast(float x) {
    return __fdividef(2.0f, 1.0f + __expf(-2.0f * x)) - 1.0f;
}

// ============ setup: pack weights/bias + transpose x + zero state ============
__global__ void setup_kernel(
    const float* __restrict__ x,
    const float* __restrict__ Wih0, const float* __restrict__ Whh0,
    const float* __restrict__ bih0, const float* __restrict__ bhh0,
    const float* __restrict__ Wih1, const float* __restrict__ Whh1,
    const float* __restrict__ bih1, const float* __restrict__ bhh1,
    const float* __restrict__ Wih2, const float* __restrict__ Whh2,
    const float* __restrict__ bih2, const float* __restrict__ bhh2)
{
    int blk = blockIdx.x, tid = threadIdx.x;
    if (blk < NL * GCTA) {
        int l = blk / GCTA, g = blk % GCTA;
        const float* Wih = (l == 0) ? Wih0 : ((l == 1) ? Wih1 : Wih2);
        const float* Whh = (l == 0) ? Whh0 : ((l == 1) ? Whh1 : Whh2);
        const float* bih = (l == 0) ? bih0 : ((l == 1) ? bih1 : bih2);
        const float* bhh = (l == 0) ? bhh0 : ((l == 1) ? bhh1 : bhh2);
        int KA = (l == 0) ? 8 : 128;
        int KP = KA + 128;
        int base = ((l == 0) ? WOFF0 : ((l == 1) ? WOFF1 : WOFF2)) + g * NR * KP;
        for (int idx = tid; idx < NR * KP; idx += blockDim.x) {
            int r = idx / KP, k = idx % KP;
            int q = r >> 2, jj = r & 3;
            int R = q * 128 + (g * NJ + jj);
            float v;
            if (k < KA) v = (l == 0) ? ((k < 6) ? Wih[R * 6 + k] : 0.0f)
                                     : Wih[R * 128 + k];
            else        v = Whh[R * 128 + (k - KA)];
            g_Wp[base + idx] = v;
        }
        if (tid < NR) {
            int r = tid, q = r >> 2, jj = r & 3;
            int R = q * 128 + (g * NJ + jj);
            g_bias[(l * GCTA + g) * NR + r] = bih[R] + bhh[R];
        }
    } else if (blk < NL * GCTA + TT) {
        int t = blk - NL * GCTA;
        if (tid < HB) {
            #pragma unroll
            for (int i = 0; i < 8; i++) {
                float v = (i < 6) ? x[(size_t)tid * (TT * 6) + t * 6 + i] : 0.0f;
                g_xT[(t * 4 + (i >> 1)) * 256 + tid * 2 + (i & 1)] = v;
            }
        }
    } else if (blk < NL * GCTA + TT + NL) {
        size_t base = (size_t)(blk - NL * GCTA - TT) * (TT + 1) * HB * HB;
        for (int i = tid; i < HB * HB; i += blockDim.x) g_H[base + i] = 0.0f;
    } else {
        for (int i = tid; i < NL * TT; i += blockDim.x) g_flags[i] = 0;
    }
}

// ---- GEMM, 16 packed cols per warp-slice, pair-packed source.
// Packed col k in [S,S+16); source pair row jp = (J + (k-S))>>1.
template<int KP>
__device__ __forceinline__ void gemm16(const float* __restrict__ src,
                                       const float* __restrict__ Wsm,
                                       int S, int J, int b, ull* acc /*16*/)
{
    #pragma unroll
    for (int kk = 0; kk < 16; kk += 4) {
        int jp = (J + kk) >> 1;
        ull h01 = ldcg64(src + jp * 256 + 2 * b);
        ull h23 = ldcg64(src + (jp + 1) * 256 + 2 * b);
        const float* wrow = Wsm + S + kk;
        #pragma unroll
        for (int r = 0; r < NR; r++) {
            ulonglong2 w = *(const ulonglong2*)(wrow + r * KP); // LDS.128 bcast
            acc[r] = ffma2(w.x, h01, acc[r]);
            acc[r] = ffma2(w.y, h23, acc[r]);
        }
    }
}

// ---- 2-col slice (layer-0 input part): pair jp = S>>1
template<int KP>
__device__ __forceinline__ void gemm2(const float* __restrict__ src,
                                      const float* __restrict__ Wsm,
                                      int S, int b, ull* acc)
{
    ull h01 = ldcg64(src + (S >> 1) * 256 + 2 * b);
    #pragma unroll
    for (int r = 0; r < NR; r++) {
        ull w = *(const ull*)(Wsm + S + r * KP);   // LDS.64 bcast
        acc[r] = ffma2(w, h01, acc[r]);
    }
}

// ---- per-layer persistent body, 1024 threads (32 warps).
// GEMM: warp = kq*4+bg? -> kq = warp>>2 (eight 16-col slices per phase),
// bg = warp&3 (four 32-batch groups), b = bg*32+lane (1 batch col/thread).
// Epilogue: threads 0..511 own (jj = tid>>7, be = tid&127); carry c state.
template<int L>
__device__ __forceinline__ void lstm_run(int g, float* Wsm, float* RD, float* bsm)
{
    constexpr int KA = (L == 0) ? 8 : 128;
    constexpr int KP = KA + 128;
    constexpr int WOFF = (L == 0) ? WOFF0 : ((L == 1) ? WOFF1 : WOFF2);

    const int tid  = threadIdx.x;
    const int lane = tid & 31;
    const int warp = tid >> 5;
    const int bg   = warp & 3;
    const int kq   = warp >> 2;          // 0..7
    const int b    = bg * 32 + lane;
    const int jj   = (tid >> 7) & 3;
    const int be   = tid & 127;
    const bool epi = (tid < 512);
    const int jrow = g * NJ + jj;

    const int wbase = WOFF + g * NR * KP;
    for (int i = tid; i < NR * KP; i += 1024) Wsm[i] = g_Wp[wbase + i];
    if (tid < NR) bsm[tid] = g_bias[(L * GCTA + g) * NR + tid];
    __syncthreads();

    float c = 0.0f;

    for (int t = 0; t < TT; t++) {
        // ---- phase A: input / below-layer contribution
        if (L > 0) {
            if (tid == 0) {
                const int* f = &g_flags[(L - 1) * TT + t];
                while (ldacq(f) < GCTA) {}
            }
            __syncthreads();
        }
        const float* SA = (L == 0)
            ? (g_xT + (size_t)t * 4 * 256)
            : (g_H + (size_t)((L - 1) * (TT + 1) + t + 1) * HB * HB);

        ull acc[NR];
        #pragma unroll
        for (int r = 0; r < NR; r++) acc[r] = 0ULL;

        if constexpr (L == 0) {
            if (kq < 4) gemm2<KP>(SA, Wsm, kq * 2, b, acc);
        } else {
            gemm16<KP>(SA, Wsm, kq * 16, kq * 16, b, acc);
        }

        // ---- phase B: own h(t-1)
        if (tid == 0 && t > 0) {
            const int* f = &g_flags[L * TT + t - 1];
            while (ldacq(f) < GCTA) {}
        }
        __syncthreads();
        const float* SB = g_H + (size_t)(L * (TT + 1) + t) * HB * HB;
        gemm16<KP>(SB, Wsm, KA + kq * 16, kq * 16, b, acc);

        #pragma unroll
        for (int r = 0; r < NR; r++) {
            float lo, hi; upk2(acc[r], lo, hi);
            RD[(kq * NR + r) * HB + b] = lo + hi;
        }
        __syncthreads();

        // ---- epilogue: threads 0..511, one (jj, be) each
        if (epi) {
            float v0 = bsm[0 * 4 + jj], v1 = bsm[1 * 4 + jj];
            float v2 = bsm[2 * 4 + jj], v3 = bsm[3 * 4 + jj];
            #pragma unroll
            for (int q2 = 0; q2 < 8; q2++) {
                v0 += RD[(q2 * NR + 0 * 4 + jj) * HB + be];
                v1 += RD[(q2 * NR + 1 * 4 + jj) * HB + be];
                v2 += RD[(q2 * NR + 2 * 4 + jj) * HB + be];
                v3 += RD[(q2 * NR + 3 * 4 + jj) * HB + be];
            }
            float iv = sigf(v0);
            float fv = sigf(v1);
            float gv = tanhf_fast(v2);
            float ov = sigf(v3);
            c = fv * c + iv * gv;
            float* Hout = g_H + (size_t)(L * (TT + 1) + t + 1) * HB * HB;
            __stcg(Hout + (jrow >> 1) * 256 + be * 2 + (jrow & 1),
                   ov * tanhf_fast(c));
        }

        __syncthreads();   // all h stores program-ordered before the release
        if (tid == 0) red_release(&g_flags[L * TT + t]);
    }
}

__global__ void __launch_bounds__(1024, 1) lstm_kernel(
    const float* __restrict__ W_out, const float* __restrict__ b_out,
    float* __restrict__ out)
{
    extern __shared__ float sm[];
    float* Wsm = sm;                       // NR*256 floats (16 KB)
    float* RD  = sm + NR * 256;            // 8*NR*HB floats (64 KB)
    float* bsm = RD + 8 * NR * HB;         // NR floats

    const int blk = blockIdx.x;
    const int l = blk >> 5, g = blk & 31;
    if (l == 0)      lstm_run<0>(g, Wsm, RD, bsm);
    else if (l == 1) lstm_run<1>(g, Wsm, RD, bsm);
    else             lstm_run<2>(g, Wsm, RD, bsm);

    // ---- head folded into CTA 64: out[b] = h2[T-1][:,b] . W_out + b_out
    if (blk == 2 * GCTA) {
        if (threadIdx.x == 0) {
            const int* f = &g_flags[2 * TT + TT - 1];
            while (ldacq(f) < GCTA) {}
        }
        __syncthreads();
        if (threadIdx.x < HB) {
            const float* h = g_H + (size_t)(2 * (TT + 1) + TT) * HB * HB;
            int b = threadIdx.x;
            float s = b_out[0];
            #pragma unroll 8
            for (int j = 0; j < HB; j++)
                s += __ldcg(h + (j >> 1) * 256 + b * 2 + (j & 1)) * W_out[j];
            out[b] = s;
        }
    }
}

extern "C" void kernel_launch(void* const* d_in, const int* in_sizes, int n_in,
                              void* d_out, int out_size)
{
    (void)in_sizes; (void)n_in; (void)out_size;

    const int SMEM_DYN = (NR * 256 + 8 * NR * HB + NR) * 4;   // 80,960 B
    cudaFuncSetAttribute(lstm_kernel,
                         cudaFuncAttributeMaxDynamicSharedMemorySize, SMEM_DYN);

    setup_kernel<<<NL * GCTA + TT + NL + 1, 256>>>(
        (const float*)d_in[0],
        (const float*)d_in[1], (const float*)d_in[2],
        (const float*)d_in[3], (const float*)d_in[4],
        (const float*)d_in[5], (const float*)d_in[6],
        (const float*)d_in[7], (const float*)d_in[8],
        (const float*)d_in[9], (const float*)d_in[10],
        (const float*)d_in[11], (const float*)d_in[12]);
    lstm_kernel<<<NL * GCTA, 1024, SMEM_DYN>>>(
        (const float*)d_in[13], (const float*)d_in[14], (float*)d_out);
}

// round 10
// speedup vs baseline: 1.3130x; 1.3130x over previous
#include <cuda_runtime.h>

#define TT   2048
#define HB   128
#define NL   3
#define GCTA 64
#define NJ   2
#define NR   8

// Layer 0: K = 8(pad) + 128 = 136 ; layers 1,2: K = 256
#define WOFF0 0
#define WOFF1 (GCTA*NR*136)
#define WOFF2 (WOFF1 + GCTA*NR*256)
#define WTOT  (WOFF2 + GCTA*NR*256)

// h history, PAIR-PACKED: element (l, slot, j, b) at
//   ((l*(TT+1)+slot)*64 + (j>>1))*256 + b*2 + (j&1)
// so {h[j][b], h[j+1][b]} (j even) is one aligned 8-byte word.
__device__ __align__(16) float g_H[(size_t)NL * (TT + 1) * HB * HB];
// x transposed, pair-packed: (t, i, b) at (t*4 + (i>>1))*256 + b*2 + (i&1), i pad 6->8
__device__ __align__(16) float g_xT[TT * 8 * HB];
__device__ float g_Wp[WTOT];
__device__ float g_bias[NL * GCTA * NR];
__device__ int   g_flags[NL * TT];

typedef unsigned long long ull;

__device__ __forceinline__ void upk2(ull v, float& lo, float& hi) {
    asm("mov.b64 {%0,%1},%2;" : "=f"(lo), "=f"(hi) : "l"(v));
}
__device__ __forceinline__ ull ffma2(ull a, ull b, ull c) {
    ull d; asm("fma.rn.f32x2 %0,%1,%2,%3;" : "=l"(d) : "l"(a), "l"(b), "l"(c));
    return d;
}
__device__ __forceinline__ ull ldcg64(const float* p) {
    ull v; asm volatile("ld.global.cg.b64 %0,[%1];" : "=l"(v) : "l"(p));
    return v;
}
__device__ __forceinline__ int ldacq(const int* p) {
    int v; asm volatile("ld.acquire.gpu.global.b32 %0,[%1];" : "=r"(v) : "l"(p) : "memory");
    return v;
}
__device__ __forceinline__ void red_release(int* p) {
    asm volatile("red.release.gpu.global.add.s32 [%0],1;" :: "l"(p) : "memory");
}
__device__ __forceinline__ float sigf(float x) {
    return __fdividef(1.0f, 1.0f + __expf(-x));
}
__device__ __forceinline__ float tanhf_fast(float x) {
    return __fdividef(2.0f, 1.0f + __expf(-2.0f * x)) - 1.0f;
}

// ============ setup: pack weights/bias + transpose x + zero state ============
__global__ void setup_kernel(
    const float* __restrict__ x,
    const float* __restrict__ Wih0, const float* __restrict__ Whh0,
    const float* __restrict__ bih0, const float* __restrict__ bhh0,
    const float* __restrict__ Wih1, const float* __restrict__ Whh1,
    const float* __restrict__ bih1, const float* __restrict__ bhh1,
    const float* __restrict__ Wih2, const float* __restrict__ Whh2,
    const float* __restrict__ bih2, const float* __restrict__ bhh2)
{
    int blk = blockIdx.x, tid = threadIdx.x;
    if (blk < NL * GCTA) {
        int l = blk / GCTA, g = blk % GCTA;
        const float* Wih = (l == 0) ? Wih0 : ((l == 1) ? Wih1 : Wih2);
        const float* Whh = (l == 0) ? Whh0 : ((l == 1) ? Whh1 : Whh2);
        const float* bih = (l == 0) ? bih0 : ((l == 1) ? bih1 : bih2);
        const float* bhh = (l == 0) ? bhh0 : ((l == 1) ? bhh1 : bhh2);
        int KA = (l == 0) ? 8 : 128;
        int KP = KA + 128;
        int base = ((l == 0) ? WOFF0 : ((l == 1) ? WOFF1 : WOFF2)) + g * NR * KP;
        for (int idx = tid; idx < NR * KP; idx += blockDim.x) {
            int r = idx / KP, k = idx % KP;
            int q = r >> 1, jj = r & 1;                 // r = q*NJ + jj
            int R = q * 128 + (g * NJ + jj);
            float v;
            if (k < KA) v = (l == 0) ? ((k < 6) ? Wih[R * 6 + k] : 0.0f)
                                     : Wih[R * 128 + k];
            else        v = Whh[R * 128 + (k - KA)];
            g_Wp[base + idx] = v;
        }
        if (tid < NR) {
            int r = tid, q = r >> 1, jj = r & 1;
            int R = q * 128 + (g * NJ + jj);
            g_bias[(l * GCTA + g) * NR + r] = bih[R] + bhh[R];
        }
    } else if (blk < NL * GCTA + TT) {
        int t = blk - NL * GCTA;
        if (tid < HB) {
            #pragma unroll
            for (int i = 0; i < 8; i++) {
                float v = (i < 6) ? x[(size_t)tid * (TT * 6) + t * 6 + i] : 0.0f;
                g_xT[(t * 4 + (i >> 1)) * 256 + tid * 2 + (i & 1)] = v;
            }
        }
    } else if (blk < NL * GCTA + TT + NL) {
        size_t base = (size_t)(blk - NL * GCTA - TT) * (TT + 1) * HB * HB;
        for (int i = tid; i < HB * HB; i += blockDim.x) g_H[base + i] = 0.0f;
    } else {
        for (int i = tid; i < NL * TT; i += blockDim.x) g_flags[i] = 0;
    }
}

// ---- GEMM, 16 packed cols, pair-packed source, 2 batch cols per thread.
// Packed col k in [S,S+16); source pair row jp = (J + (k-S))>>1.
template<int KP>
__device__ __forceinline__ void gemm16_2b(const float* __restrict__ src,
                                          const float* __restrict__ Wsm,
                                          int S, int J, int b0, ull* acc /*16*/)
{
    #pragma unroll
    for (int kk = 0; kk < 16; kk += 4) {
        int jp = (J + kk) >> 1;
        const float* sc = src + jp * 256 + 2 * b0;
        ull h01 = ldcg64(sc);
        ull h23 = ldcg64(sc + 256);
        ull g01 = ldcg64(sc + 64);          // batch col b0+32 -> +64 floats
        ull g23 = ldcg64(sc + 256 + 64);
        const float* wrow = Wsm + S + kk;
        #pragma unroll
        for (int r = 0; r < NR; r++) {
            ulonglong2 w = *(const ulonglong2*)(wrow + r * KP); // LDS.128 bcast
            acc[r]      = ffma2(w.x, h01, acc[r]);
            acc[r]      = ffma2(w.y, h23, acc[r]);
            acc[NR + r] = ffma2(w.x, g01, acc[NR + r]);
            acc[NR + r] = ffma2(w.y, g23, acc[NR + r]);
        }
    }
}

// ---- 2-col slice (layer-0 input part): pair jp = S>>1
template<int KP>
__device__ __forceinline__ void gemm2_2b(const float* __restrict__ src,
                                         const float* __restrict__ Wsm,
                                         int S, int b0, ull* acc)
{
    const float* sc = src + (S >> 1) * 256 + 2 * b0;
    ull h01 = ldcg64(sc);
    ull g01 = ldcg64(sc + 64);
    #pragma unroll
    for (int r = 0; r < NR; r++) {
        ull w = *(const ull*)(Wsm + S + r * KP);   // LDS.64 bcast
        acc[r]      = ffma2(w, h01, acc[r]);
        acc[NR + r] = ffma2(w, g01, acc[NR + r]);
    }
}

// ---- per-layer persistent body, 512 threads (16 warps), 2 CTAs/SM.
// GEMM: warp = kq*2+bg (kq = 0..7 K-slices of 16, bg = 0..1); thread handles
// batch cols b0 = bg*64+lane and b0+32.
// Epilogue: threads 0..255 own (jj = tid>>7, be = tid&127); carry c state.
template<int L>
__device__ __forceinline__ void lstm_run(int g, float* Wsm, float* RD, float* bsm)
{
    constexpr int KA = (L == 0) ? 8 : 128;
    constexpr int KP = KA + 128;
    constexpr int WOFF = (L == 0) ? WOFF0 : ((L == 1) ? WOFF1 : WOFF2);

    const int tid  = threadIdx.x;
    const int lane = tid & 31;
    const int warp = tid >> 5;
    const int bg   = warp & 1;
    const int kq   = warp >> 1;          // 0..7
    const int b0   = bg * 64 + lane;
    const int jj   = tid >> 7;           // epilogue: 0..1 (tid < 256)
    const int be   = tid & 127;
    const int jrow = g * NJ + jj;

    const int wbase = WOFF + g * NR * KP;
    for (int i = tid; i < NR * KP; i += 512) Wsm[i] = g_Wp[wbase + i];
    if (tid < NR) bsm[tid] = g_bias[(L * GCTA + g) * NR + tid];
    __syncthreads();

    float c = 0.0f;

    for (int t = 0; t < TT; t++) {
        // ---- phase A: input / below-layer contribution
        if (L > 0) {
            if (tid == 0) {
                const int* f = &g_flags[(L - 1) * TT + t];
                while (ldacq(f) < GCTA) {}
            }
            __syncthreads();
        }
        const float* SA = (L == 0)
            ? (g_xT + (size_t)t * 4 * 256)
            : (g_H + (size_t)((L - 1) * (TT + 1) + t + 1) * HB * HB);

        ull acc[2 * NR];
        #pragma unroll
        for (int r = 0; r < 2 * NR; r++) acc[r] = 0ULL;

        if constexpr (L == 0) {
            if (kq < 4) gemm2_2b<KP>(SA, Wsm, kq * 2, b0, acc);
        } else {
            gemm16_2b<KP>(SA, Wsm, kq * 16, kq * 16, b0, acc);
        }

        // ---- phase B: own h(t-1) (own-flag wait overlapped by phase A)
        if (tid == 0 && t > 0) {
            const int* f = &g_flags[L * TT + t - 1];
            while (ldacq(f) < GCTA) {}
        }
        __syncthreads();
        const float* SB = g_H + (size_t)(L * (TT + 1) + t) * HB * HB;
        gemm16_2b<KP>(SB, Wsm, KA + kq * 16, kq * 16, b0, acc);

        #pragma unroll
        for (int r = 0; r < NR; r++) {
            float lo, hi; upk2(acc[r], lo, hi);
            RD[(kq * NR + r) * HB + b0] = lo + hi;
            upk2(acc[NR + r], lo, hi);
            RD[(kq * NR + r) * HB + b0 + 32] = lo + hi;
        }
        __syncthreads();

        // ---- epilogue: threads 0..255, one (jj, be) each
        if (tid < 256) {
            float v0 = bsm[0 * NJ + jj], v1 = bsm[1 * NJ + jj];
            float v2 = bsm[2 * NJ + jj], v3 = bsm[3 * NJ + jj];
            #pragma unroll
            for (int q2 = 0; q2 < 8; q2++) {
                v0 += RD[(q2 * NR + 0 * NJ + jj) * HB + be];
                v1 += RD[(q2 * NR + 1 * NJ + jj) * HB + be];
                v2 += RD[(q2 * NR + 2 * NJ + jj) * HB + be];
                v3 += RD[(q2 * NR + 3 * NJ + jj) * HB + be];
            }
            float iv = sigf(v0);
            float fv = sigf(v1);
            float gv = tanhf_fast(v2);
            float ov = sigf(v3);
            c = fv * c + iv * gv;
            float* Hout = g_H + (size_t)(L * (TT + 1) + t + 1) * HB * HB;
            __stcg(Hout + (jrow >> 1) * 256 + be * 2 + (jrow & 1),
                   ov * tanhf_fast(c));
        }

        __syncthreads();   // all h stores program-ordered before the release
        if (tid == 0) red_release(&g_flags[L * TT + t]);
    }
}

__global__ void __launch_bounds__(512, 2) lstm_kernel(
    const float* __restrict__ W_out, const float* __restrict__ b_out,
    float* __restrict__ out)
{
    extern __shared__ float sm[];
    float* Wsm = sm;                       // NR*256 floats (8 KB)
    float* RD  = sm + NR * 256;            // 8*NR*HB floats (32 KB)
    float* bsm = RD + 8 * NR * HB;         // NR floats

    const int blk = blockIdx.x;
    const int l = blk >> 6, g = blk & 63;
    if (l == 0)      lstm_run<0>(g, Wsm, RD, bsm);
    else if (l == 1) lstm_run<1>(g, Wsm, RD, bsm);
    else             lstm_run<2>(g, Wsm, RD, bsm);

    // ---- head folded into CTA 128: out[b] = h2[T-1][:,b] . W_out + b_out
    if (blk == 2 * GCTA) {
        if (threadIdx.x == 0) {
            const int* f = &g_flags[2 * TT + TT - 1];
            while (ldacq(f) < GCTA) {}
        }
        __syncthreads();
        if (threadIdx.x < HB) {
            const float* h = g_H + (size_t)(2 * (TT + 1) + TT) * HB * HB;
            int b = threadIdx.x;
            float s = b_out[0];
            #pragma unroll 8
            for (int j = 0; j < HB; j++)
                s += __ldcg(h + (j >> 1) * 256 + b * 2 + (j & 1)) * W_out[j];
            out[b] = s;
        }
    }
}

extern "C" void kernel_launch(void* const* d_in, const int* in_sizes, int n_in,
                              void* d_out, int out_size)
{
    (void)in_sizes; (void)n_in; (void)out_size;

    const int SMEM_DYN = (NR * 256 + 8 * NR * HB + NR) * 4;   // 40,992 B
    cudaFuncSetAttribute(lstm_kernel,
                         cudaFuncAttributeMaxDynamicSharedMemorySize, SMEM_DYN);

    setup_kernel<<<NL * GCTA + TT + NL + 1, 256>>>(
        (const float*)d_in[0],
        (const float*)d_in[1], (const float*)d_in[2],
        (const float*)d_in[3], (const float*)d_in[4],
        (const float*)d_in[5], (const float*)d_in[6],
        (const float*)d_in[7], (const float*)d_in[8],
        (const float*)d_in[9], (const float*)d_in[10],
        (const float*)d_in[11], (const float*)d_in[12]);
    lstm_kernel<<<NL * GCTA, 512, SMEM_DYN>>>(
        (const float*)d_in[13], (const float*)d_in[14], (float*)d_out);
}